// round 13
// baseline (speedup 1.0000x reference)
#include <cuda_runtime.h>
#include <math.h>

#define BATCH 8
#define NA    261888
#define KTOP  6000
#define PROP  1000
#define SHIFT 14
#define NBUCK (1 << 18)
#define CAP   8192
#define SORTN 8192

#define SLOTS    32
#define SPILLCAP 32768

#define CELLG    16
#define NCELL    (CELLG * CELLG)
#define CELLCAP  768

/* ---------------- device scratch (static: no allocation allowed) -------- */
__device__ unsigned int       g_hist[BATCH][NBUCK];
__device__ unsigned int       g_maxbucket[BATCH];
__device__ int                g_thresh[BATCH];
__device__ unsigned int       g_total[BATCH];
__device__ unsigned long long g_cand[BATCH][CAP];
__device__ float4             g_boxes[BATCH * KTOP];
__device__ float              g_areas[BATCH * KTOP];
__device__ unsigned int       g_pcnt[BATCH][KTOP];           /* pairs per row */
__device__ unsigned int       g_padj[BATCH][KTOP][SLOTS];    /* adjacency     */
__device__ unsigned int       g_spill[BATCH][SPILLCAP];      /* (i<<16)|j     */
__device__ unsigned int       g_spillcnt[BATCH];
__device__ unsigned int       g_ccnt[BATCH][NCELL];          /* boxes / cell  */
__device__ unsigned int       g_cells[BATCH][NCELL][CELLCAP];
__device__ unsigned int       g_cellovf[BATCH];              /* overflow flag */

/* order-preserving float -> uint key */
__device__ __forceinline__ unsigned int fkey(float s) {
    unsigned int u = __float_as_uint(s);
    return u ^ ((unsigned int)((int)u >> 31) | 0x80000000u);
}

/* ---------------- kernel 0: clear scratch ------------------------------ */
__global__ void clear_kernel() {
    size_t tid    = (size_t)blockIdx.x * blockDim.x + threadIdx.x;
    size_t stride = (size_t)gridDim.x * blockDim.x;
    uint4* h4 = (uint4*)&g_hist[0][0];
    size_t n4 = (size_t)BATCH * NBUCK / 4;
    uint4 z4 = make_uint4(0, 0, 0, 0);
    for (size_t i = tid; i < n4; i += stride) h4[i] = z4;
    unsigned long long* c = &g_cand[0][0];
    for (size_t i = tid; i < (size_t)BATCH * CAP; i += stride) c[i] = 0ull;
    unsigned int* pc = &g_pcnt[0][0];
    for (size_t i = tid; i < (size_t)BATCH * KTOP; i += stride) pc[i] = 0u;
    unsigned int* cc = &g_ccnt[0][0];
    for (size_t i = tid; i < (size_t)BATCH * NCELL; i += stride) cc[i] = 0u;
    if (tid < BATCH) {
        g_maxbucket[tid] = 0u; g_spillcnt[tid] = 0u; g_cellovf[tid] = 0u;
    }
}

/* ---------------- kernel 1: per-batch bucket histogram ------------------ */
__global__ void hist_kernel(const float* __restrict__ probs) {
    int b = blockIdx.y;
    const float* p = probs + (size_t)b * NA * 2;
    unsigned int lmax = 0;
    for (int a = blockIdx.x * blockDim.x + threadIdx.x; a < NA;
         a += gridDim.x * blockDim.x) {
        unsigned int key = fkey(p[2 * a + 1]);
        unsigned int bk = key >> SHIFT;
        atomicAdd(&g_hist[b][bk], 1u);
        lmax = max(lmax, bk);
    }
    __shared__ unsigned int sm[256];
    sm[threadIdx.x] = lmax;
    __syncthreads();
    for (int o = 128; o > 0; o >>= 1) {
        if (threadIdx.x < o) sm[threadIdx.x] = max(sm[threadIdx.x], sm[threadIdx.x + o]);
        __syncthreads();
    }
    if (threadIdx.x == 0) atomicMax(&g_maxbucket[b], sm[0]);
}

/* ---------------- kernel 2: find threshold bucket, write fill bases ----- */
__global__ void findthresh_kernel() {
    int b = blockIdx.x, tid = threadIdx.x;
    __shared__ unsigned int scnt[256];
    __shared__ unsigned int s_running;
    if (tid == 0) s_running = 0;
    __syncthreads();
    int start = (int)g_maxbucket[b];
    for (int cs = start; cs >= 0; cs -= 256) {
        int bk = cs - tid;
        unsigned int c = (bk >= 0) ? g_hist[b][bk] : 0u;
        scnt[tid] = c;
        __syncthreads();
        for (int off = 1; off < 256; off <<= 1) {
            unsigned int v = (tid >= off) ? scnt[tid - off] : 0u;
            __syncthreads();
            scnt[tid] += v;
            __syncthreads();
        }
        unsigned int incl = scnt[tid];
        unsigned int excl = incl - c;
        unsigned int run = s_running;
        if (bk >= 0 && run + excl < KTOP) {
            g_hist[b][bk] = run + excl;
            if (run + incl >= KTOP) {
                g_thresh[b] = bk;
                g_total[b]  = run + incl;
            }
        }
        __syncthreads();
        if (tid == 0) s_running = run + scnt[255];
        __syncthreads();
        if (s_running >= KTOP) break;
    }
}

/* ---------------- kernel 3: compact candidates (grouped by bucket) ------ */
__global__ void compact_kernel(const float* __restrict__ probs) {
    int b = blockIdx.y;
    int tb = g_thresh[b];
    const float* p = probs + (size_t)b * NA * 2;
    for (int a = blockIdx.x * blockDim.x + threadIdx.x; a < NA;
         a += gridDim.x * blockDim.x) {
        unsigned int key = fkey(p[2 * a + 1]);
        unsigned int bk = key >> SHIFT;
        if ((int)bk >= tb) {
            unsigned int pos = atomicAdd(&g_hist[b][bk], 1u);
            if (pos < CAP)
                g_cand[b][pos] =
                    ((unsigned long long)key << 32) | (unsigned int)(~a);
        }
    }
}

/* ---------------- kernel 4: bitonic sort + gather + box decode ---------- */
__global__ void __launch_bounds__(1024, 1)
sort_gather_kernel(const float* __restrict__ bbox,
                   const float* __restrict__ anchors) {
    extern __shared__ unsigned long long s[];
    int b = blockIdx.x, tid = threadIdx.x;
    for (int i = tid; i < SORTN; i += blockDim.x) s[i] = g_cand[b][i];
    __syncthreads();
    for (int k = 2; k <= SORTN; k <<= 1) {
        for (int j = k >> 1; j > 0; j >>= 1) {
            for (int i = tid; i < SORTN; i += blockDim.x) {
                int ixj = i ^ j;
                if (ixj > i) {
                    unsigned long long x = s[i], y = s[ixj];
                    bool up = ((i & k) == 0);
                    if (up ? (x < y) : (x > y)) { s[i] = y; s[ixj] = x; }
                }
            }
            __syncthreads();
        }
    }
    const float4* anc = (const float4*)(anchors + (size_t)b * NA * 4);
    const float4* dl  = (const float4*)(bbox    + (size_t)b * NA * 4);
    for (int i = tid; i < KTOP; i += blockDim.x) {
        unsigned int idx = ~(unsigned int)(s[i]);
        float4 a4 = anc[idx];
        float4 r4 = dl[idx];
        float d0 = __fmul_rn(r4.x, 0.1f);
        float d1 = __fmul_rn(r4.y, 0.1f);
        float d2 = __fmul_rn(r4.z, 0.2f);
        float d3 = __fmul_rn(r4.w, 0.2f);
        float h  = __fsub_rn(a4.z, a4.x);
        float w  = __fsub_rn(a4.w, a4.y);
        float cy = __fadd_rn(__fadd_rn(a4.x, __fmul_rn(0.5f, h)), __fmul_rn(d0, h));
        float cx = __fadd_rn(__fadd_rn(a4.y, __fmul_rn(0.5f, w)), __fmul_rn(d1, w));
        float h2 = __fmul_rn(h, expf(d2));
        float w2 = __fmul_rn(w, expf(d3));
        float y1 = __fsub_rn(cy, __fmul_rn(0.5f, h2));
        float x1 = __fsub_rn(cx, __fmul_rn(0.5f, w2));
        float y2 = __fadd_rn(y1, h2);
        float x2 = __fadd_rn(x1, w2);
        y1 = fminf(fmaxf(y1, 0.0f), 1.0f);
        x1 = fminf(fmaxf(x1, 0.0f), 1.0f);
        y2 = fminf(fmaxf(y2, 0.0f), 1.0f);
        x2 = fminf(fmaxf(x2, 0.0f), 1.0f);
        g_boxes[b * KTOP + i] = make_float4(y1, x1, y2, x2);
        g_areas[b * KTOP + i] = __fmul_rn(__fsub_rn(y2, y1), __fsub_rn(x2, x1));
    }
}

/* ------- kernel 5a: assign boxes to grid cells -------------------------- */
__global__ void cell_assign_kernel() {
    int b = blockIdx.y;
    int i = blockIdx.x * blockDim.x + threadIdx.x;
    if (i >= KTOP) return;
    float4 bx = g_boxes[b * KTOP + i];
    int cy0 = min(CELLG - 1, (int)(bx.x * CELLG));
    int cx0 = min(CELLG - 1, (int)(bx.y * CELLG));
    int cy1 = min(CELLG - 1, (int)(bx.z * CELLG));
    int cx1 = min(CELLG - 1, (int)(bx.w * CELLG));
    for (int cy = cy0; cy <= cy1; ++cy)
        for (int cx = cx0; cx <= cx1; ++cx) {
            int cell = cy * CELLG + cx;
            unsigned int pos = atomicAdd(&g_ccnt[b][cell], 1u);
            if (pos < CELLCAP) g_cells[b][cell][pos] = (unsigned int)i;
            else               g_cellovf[b] = 1u;
        }
}

/* ------- kernel 5b: per-cell pair evaluation (row-loop, exact dedup) ---- */
__global__ void __launch_bounds__(256)
cell_pairs_kernel() {
    int cell = blockIdx.x;
    int b    = blockIdx.y;
    int cellx = cell & (CELLG - 1);
    int celly = cell >> 4;
    __shared__ float4         sbx[CELLCAP];
    __shared__ unsigned short sid[CELLCAP];
    int n = (int)min(g_ccnt[b][cell], (unsigned int)CELLCAP);
    for (int t = threadIdx.x; t < n; t += blockDim.x) {
        unsigned int gi = g_cells[b][cell][t];
        sid[t] = (unsigned short)gi;
        sbx[t] = g_boxes[b * KTOP + gi];
    }
    __syncthreads();
    /* row-loop: thread owns row a; A stays in registers; b walks smem */
    for (int a = threadIdx.x; a < n - 1; a += blockDim.x) {
        float4 A = sbx[a];
        float aA = __fmul_rn(__fsub_rn(A.z, A.x), __fsub_rn(A.w, A.y));
        int idA = (int)sid[a];
        for (int bq = a + 1; bq < n; ++bq) {
            float4 Bx = sbx[bq];
            float yy1 = fmaxf(A.x, Bx.x);
            float xx1 = fmaxf(A.y, Bx.y);
            float yy2 = fminf(A.z, Bx.z);
            float xx2 = fminf(A.w, Bx.w);
            float inter = __fmul_rn(fmaxf(__fsub_rn(yy2, yy1), 0.0f),
                                    fmaxf(__fsub_rn(xx2, xx1), 0.0f));
            if (inter > 0.0f) {
                /* canonical cell = cell of (yy1, xx1): dedup across cells */
                int ccy = min(CELLG - 1, (int)(yy1 * CELLG));
                int ccx = min(CELLG - 1, (int)(xx1 * CELLG));
                if (ccy == celly && ccx == cellx) {
                    float aB = __fmul_rn(__fsub_rn(Bx.z, Bx.x),
                                         __fsub_rn(Bx.w, Bx.y));
                    float uni = __fsub_rn(__fadd_rn(aA, aB), inter);
                    if (uni > 0.0f && !(__fdiv_rn(inter, uni) <= 0.7f)) {
                        int ib = (int)sid[bq];
                        int i = min(idA, ib), j = max(idA, ib);
                        unsigned int pos = atomicAdd(&g_pcnt[b][i], 1u);
                        if (pos < SLOTS) {
                            g_padj[b][i][pos] = (unsigned int)j;
                        } else {
                            unsigned int sp2 = atomicAdd(&g_spillcnt[b], 1u);
                            if (sp2 < SPILLCAP)
                                g_spill[b][sp2] =
                                    ((unsigned int)i << 16) | (unsigned int)j;
                        }
                    }
                }
            }
        }
    }
}

/* ------- kernel 5c: brute-force fallback (only if a cell overflowed) ---- */
#define MBK_THREADS 256
#define MBK_RPW     8
#define MBK_ROWS    (8 * MBK_RPW)
#define MBK_CHUNK   2048

__global__ void __launch_bounds__(MBK_THREADS)
pair_fallback_kernel() {
    int b = blockIdx.y;
    if (!g_cellovf[b]) return;                  /* common case: exit */
    int rowbase = blockIdx.x * MBK_ROWS;
    int warp    = threadIdx.x >> 5;
    int lane    = threadIdx.x & 31;
    int i0      = rowbase + warp * MBK_RPW;

    __shared__ float4 sbox[MBK_CHUNK];
    const float4* boxes = g_boxes + b * KTOP;
    const float*  areas = g_areas + b * KTOP;

    float4 rb[MBK_RPW]; float ra[MBK_RPW];
#pragma unroll
    for (int r = 0; r < MBK_RPW; ++r) {
        int i = i0 + r;
        if (i < KTOP) { rb[r] = boxes[i]; ra[r] = areas[i]; }
        else { rb[r] = make_float4(0.f, 0.f, 0.f, 0.f); ra[r] = 0.f; }
    }
    for (int chunk = 0; chunk < KTOP; chunk += MBK_CHUNK) {
        int cn = min(MBK_CHUNK, KTOP - chunk);
        __syncthreads();
        for (int t = threadIdx.x; t < cn; t += MBK_THREADS)
            sbox[t] = boxes[chunk + t];
        __syncthreads();
        if (chunk + cn <= rowbase) continue;
        int wstart = (i0 + 1 > chunk) ? ((i0 + 1 - chunk) >> 5) : 0;
        int wend   = (cn + 31) >> 5;
        for (int wd = wstart; wd < wend; ++wd) {
            int j = chunk + wd * 32 + lane;
            float4 cbx = sbox[wd * 32 + lane];
            float cax = __fmul_rn(__fsub_rn(cbx.z, cbx.x),
                                  __fsub_rn(cbx.w, cbx.y));
            bool jok = (j < KTOP);
            unsigned int supmask = 0;
#pragma unroll
            for (int r = 0; r < MBK_RPW; ++r) {
                float yy1 = fmaxf(rb[r].x, cbx.x);
                float xx1 = fmaxf(rb[r].y, cbx.y);
                float yy2 = fminf(rb[r].z, cbx.z);
                float xx2 = fminf(rb[r].w, cbx.w);
                float inter = __fmul_rn(fmaxf(__fsub_rn(yy2, yy1), 0.0f),
                                        fmaxf(__fsub_rn(xx2, xx1), 0.0f));
                bool sup = false;
                if (inter > 0.0f && jok && j > i0 + r) {
                    float uni = __fsub_rn(__fadd_rn(ra[r], cax), inter);
                    if (uni > 0.0f)
                        sup = !(__fdiv_rn(inter, uni) <= 0.7f);
                }
                supmask |= sup ? (1u << r) : 0u;
            }
            if (__any_sync(0xFFFFFFFFu, supmask != 0u)) {
                while (supmask) {
                    int r = __ffs(supmask) - 1;
                    supmask &= supmask - 1u;
                    int i = i0 + r;
                    unsigned int pos = atomicAdd(&g_pcnt[b][i], 1u);
                    if (pos < SLOTS) {
                        g_padj[b][i][pos] = (unsigned int)j;
                    } else {
                        unsigned int sp2 = atomicAdd(&g_spillcnt[b], 1u);
                        if (sp2 < SPILLCAP)
                            g_spill[b][sp2] =
                                ((unsigned int)i << 16) | (unsigned int)j;
                    }
                }
            }
        }
    }
}

/* ------- kernel 6: sparse serial greedy pass ---------------------------- */
__global__ void __launch_bounds__(32, 1)
nms_serial_kernel(float* __restrict__ out) {
    int b    = blockIdx.x;
    int lane = threadIdx.x;
    __shared__ unsigned long long sbm[94];
    __shared__ unsigned long long szero[94];
    __shared__ unsigned char      scnt[KTOP];
    __shared__ int                s_picks[PROP];
    __shared__ int                s_ctl[2];

    const float* areas = g_areas + b * KTOP;

    for (int wu = lane; wu < 94; wu += 32)
        sbm[wu] = (wu < 93) ? ~0ull : ((1ull << 48) - 1ull);

    for (int wu = 0; wu < 94; ++wu) {
        int i1 = wu * 64 + lane;
        int i2 = i1 + 32;
        bool z1 = (i1 < KTOP) && (areas[i1] == 0.0f);
        bool z2 = (i2 < KTOP) && (areas[i2] == 0.0f);
        unsigned int lo = __ballot_sync(0xFFFFFFFFu, z1);
        unsigned int hi = __ballot_sync(0xFFFFFFFFu, z2);
        if (lane == 0)
            szero[wu] = ((unsigned long long)hi << 32) | lo;
    }

    for (int i = lane; i < KTOP; i += 32) {
        unsigned int c = g_pcnt[b][i];
        scnt[i] = (unsigned char)(c > 255u ? 255u : c);
    }
    __syncwarp();

    if (lane == 0) {
        int cur = 0, sp = 0, fill = -1;
        int sc = (int)g_spillcnt[b];
        if (sc > SPILLCAP) sc = SPILLCAP;
        while (sp < PROP) {
            int wu = cur >> 6;
            unsigned long long w =
                (wu < 94) ? (sbm[wu] & (~0ull << (cur & 63))) : 0ull;
            while (!w) {
                if (++wu >= 94) break;
                w = sbm[wu];
            }
            if (wu >= 94) break;
            int i = (wu << 6) + (__ffsll((long long)w) - 1);
            s_picks[sp++] = i;
            if ((szero[wu] >> (i & 63)) & 1ull) {
                fill = i;
                break;
            }
            cur = i + 1;
            int n = scnt[i];
            if (n) {
                const unsigned int* adj = g_padj[b][i];
                int mslots = n < SLOTS ? n : SLOTS;
                for (int t = 0; t < mslots; ++t) {
                    int j = (int)adj[t];
                    sbm[j >> 6] &= ~(1ull << (j & 63));
                }
                if (n > SLOTS) {
                    for (int k = 0; k < sc; ++k) {
                        unsigned int p = g_spill[b][k];
                        if ((int)(p >> 16) == i) {
                            int j = (int)(p & 0xFFFFu);
                            sbm[j >> 6] &= ~(1ull << (j & 63));
                        }
                    }
                }
            }
        }
        s_ctl[0] = sp;
        s_ctl[1] = fill;
    }
    __syncwarp();
    int step = s_ctl[0];
    int fill = s_ctl[1];

    for (int s2 = step + lane; s2 < PROP; s2 += 32) s_picks[s2] = fill;
    __syncwarp();
    const float4* boxes = g_boxes + b * KTOP;
    float4* o = (float4*)out + b * PROP;
    for (int s2 = lane; s2 < PROP; s2 += 32) {
        int p = s_picks[s2];
        o[s2] = (p >= 0) ? boxes[p] : make_float4(0.f, 0.f, 0.f, 0.f);
    }
}

/* ---------------- launch ------------------------------------------------ */
extern "C" void kernel_launch(void* const* d_in, const int* in_sizes, int n_in,
                              void* d_out, int out_size) {
    const float* probs   = (const float*)d_in[0];  /* (B, A, 2) */
    const float* bbox    = (const float*)d_in[1];  /* (B, A, 4) */
    const float* anchors = (const float*)d_in[2];  /* (B, A, 4) */
    float* out = (float*)d_out;                    /* (B, 1000, 4) */

    cudaFuncSetAttribute(sort_gather_kernel,
                         cudaFuncAttributeMaxDynamicSharedMemorySize, SORTN * 8);

    clear_kernel<<<1024, 256>>>();
    dim3 hg(256, BATCH);
    hist_kernel<<<hg, 256>>>(probs);
    findthresh_kernel<<<BATCH, 256>>>();
    compact_kernel<<<hg, 256>>>(probs);
    sort_gather_kernel<<<BATCH, 1024, SORTN * 8>>>(bbox, anchors);
    dim3 ag((KTOP + 255) / 256, BATCH);
    cell_assign_kernel<<<ag, 256>>>();
    dim3 cg(NCELL, BATCH);
    cell_pairs_kernel<<<cg, 256>>>();
    dim3 fg((KTOP + MBK_ROWS - 1) / MBK_ROWS, BATCH);
    pair_fallback_kernel<<<fg, MBK_THREADS>>>();
    nms_serial_kernel<<<BATCH, 32>>>(out);
}

// round 14
// speedup vs baseline: 1.1953x; 1.1953x over previous
#include <cuda_runtime.h>
#include <math.h>

#define BATCH 8
#define NA    261888
#define KTOP  6000
#define PROP  1000
#define SHIFT 14
#define NBUCK (1 << 18)
#define CAP   8192
#define SORTN 8192
#define SEGP  1024

#define SLOTS    32
#define SPILLCAP 32768

#define CELLG    16
#define NCELL    (CELLG * CELLG)
#define CELLCAP  768

/* ---------------- device scratch (static: no allocation allowed) -------- */
__device__ unsigned int       g_hist[BATCH][NBUCK];
__device__ unsigned int       g_base[BATCH][NBUCK];
__device__ unsigned int       g_maxbucket[BATCH];
__device__ int                g_thresh[BATCH];
__device__ unsigned int       g_total[BATCH];
__device__ unsigned int       g_segovf[BATCH];
__device__ unsigned long long g_cand[BATCH][CAP];
__device__ float4             g_boxes[BATCH * KTOP];
__device__ float              g_areas[BATCH * KTOP];
__device__ unsigned int       g_pcnt[BATCH][KTOP];           /* pairs per row */
__device__ unsigned int       g_padj[BATCH][KTOP][SLOTS];    /* adjacency     */
__device__ unsigned int       g_spill[BATCH][SPILLCAP];      /* (i<<16)|j     */
__device__ unsigned int       g_spillcnt[BATCH];
__device__ unsigned int       g_ccnt[BATCH][NCELL];          /* boxes / cell  */
__device__ unsigned int       g_cells[BATCH][NCELL][CELLCAP];
__device__ unsigned int       g_cellovf[BATCH];              /* overflow flag */

/* order-preserving float -> uint key */
__device__ __forceinline__ unsigned int fkey(float s) {
    unsigned int u = __float_as_uint(s);
    return u ^ ((unsigned int)((int)u >> 31) | 0x80000000u);
}

/* ---------------- kernel 0: clear scratch ------------------------------ */
__global__ void clear_kernel() {
    size_t tid    = (size_t)blockIdx.x * blockDim.x + threadIdx.x;
    size_t stride = (size_t)gridDim.x * blockDim.x;
    uint4* h4 = (uint4*)&g_hist[0][0];
    size_t n4 = (size_t)BATCH * NBUCK / 4;
    uint4 z4 = make_uint4(0, 0, 0, 0);
    for (size_t i = tid; i < n4; i += stride) h4[i] = z4;
    unsigned long long* c = &g_cand[0][0];
    for (size_t i = tid; i < (size_t)BATCH * CAP; i += stride) c[i] = 0ull;
    unsigned int* pc = &g_pcnt[0][0];
    for (size_t i = tid; i < (size_t)BATCH * KTOP; i += stride) pc[i] = 0u;
    unsigned int* cc = &g_ccnt[0][0];
    for (size_t i = tid; i < (size_t)BATCH * NCELL; i += stride) cc[i] = 0u;
    if (tid < BATCH) {
        g_maxbucket[tid] = 0u; g_spillcnt[tid] = 0u;
        g_cellovf[tid] = 0u;  g_segovf[tid] = 0u;
    }
}

/* ---------------- kernel 1: per-batch bucket histogram ------------------ */
__global__ void hist_kernel(const float* __restrict__ probs) {
    int b = blockIdx.y;
    const float* p = probs + (size_t)b * NA * 2;
    unsigned int lmax = 0;
    for (int a = blockIdx.x * blockDim.x + threadIdx.x; a < NA;
         a += gridDim.x * blockDim.x) {
        unsigned int key = fkey(p[2 * a + 1]);
        unsigned int bk = key >> SHIFT;
        atomicAdd(&g_hist[b][bk], 1u);
        lmax = max(lmax, bk);
    }
    __shared__ unsigned int sm[256];
    sm[threadIdx.x] = lmax;
    __syncthreads();
    for (int o = 128; o > 0; o >>= 1) {
        if (threadIdx.x < o) sm[threadIdx.x] = max(sm[threadIdx.x], sm[threadIdx.x + o]);
        __syncthreads();
    }
    if (threadIdx.x == 0) atomicMax(&g_maxbucket[b], sm[0]);
}

/* ---------------- kernel 2: find threshold bucket, write fill bases ----- */
__global__ void findthresh_kernel() {
    int b = blockIdx.x, tid = threadIdx.x;
    __shared__ unsigned int scnt[256];
    __shared__ unsigned int s_running;
    if (tid == 0) s_running = 0;
    __syncthreads();
    int start = (int)g_maxbucket[b];
    for (int cs = start; cs >= 0; cs -= 256) {
        int bk = cs - tid;
        unsigned int c = (bk >= 0) ? g_hist[b][bk] : 0u;
        scnt[tid] = c;
        __syncthreads();
        for (int off = 1; off < 256; off <<= 1) {
            unsigned int v = (tid >= off) ? scnt[tid - off] : 0u;
            __syncthreads();
            scnt[tid] += v;
            __syncthreads();
        }
        unsigned int incl = scnt[tid];
        unsigned int excl = incl - c;
        unsigned int run = s_running;
        if (bk >= 0 && run + excl < KTOP) {
            g_hist[b][bk] = run + excl;       /* counting-sort fill base */
            g_base[b][bk] = run + excl;       /* snapshot for segsort    */
            if (run + incl >= KTOP) {
                g_thresh[b] = bk;
                g_total[b]  = run + incl;
            }
        }
        __syncthreads();
        if (tid == 0) s_running = run + scnt[255];
        __syncthreads();
        if (s_running >= KTOP) break;
    }
}

/* ---------------- kernel 3: compact candidates (grouped by bucket) ------ */
__global__ void compact_kernel(const float* __restrict__ probs) {
    int b = blockIdx.y;
    int tb = g_thresh[b];
    const float* p = probs + (size_t)b * NA * 2;
    for (int a = blockIdx.x * blockDim.x + threadIdx.x; a < NA;
         a += gridDim.x * blockDim.x) {
        unsigned int key = fkey(p[2 * a + 1]);
        unsigned int bk = key >> SHIFT;
        if ((int)bk >= tb) {
            unsigned int pos = atomicAdd(&g_hist[b][bk], 1u);
            if (pos < CAP)
                g_cand[b][pos] =
                    ((unsigned long long)key << 32) | (unsigned int)(~a);
        }
    }
}

/* ------- kernel 4a: per-bucket block bitonic sort ----------------------- */
/* Buckets are disjoint, already in descending-bucket order (bases from     */
/* findthresh).  bucket = key>>14, so cross-segment order is already the    */
/* global order; sorting each segment descending reproduces the full sort.  */
__global__ void __launch_bounds__(256)
segsort_kernel() {
    int b  = blockIdx.y;
    int tb = g_thresh[b];
    int mb = (int)g_maxbucket[b];
    __shared__ unsigned long long s[SEGP];
    for (int bk = tb + blockIdx.x; bk <= mb; bk += gridDim.x) {
        unsigned int base = g_base[b][bk];
        unsigned int end  = g_hist[b][bk];    /* end offset after compact */
        if (end > CAP) { g_segovf[b] = 1u; continue; }
        int n = (int)(end - base);
        if (n <= 1) continue;
        if (n > SEGP) { g_segovf[b] = 1u; continue; }
        for (int t = threadIdx.x; t < SEGP; t += 256)
            s[t] = (t < n) ? g_cand[b][base + t] : 0ull;   /* 0 sorts last */
        __syncthreads();
        for (int k = 2; k <= SEGP; k <<= 1) {
            for (int j = k >> 1; j > 0; j >>= 1) {
                for (int t = threadIdx.x; t < SEGP; t += 256) {
                    int ixj = t ^ j;
                    if (ixj > t) {
                        unsigned long long x = s[t], y = s[ixj];
                        bool up = ((t & k) == 0);          /* descending */
                        if (up ? (x < y) : (x > y)) { s[t] = y; s[ixj] = x; }
                    }
                }
                __syncthreads();
            }
        }
        for (int t = threadIdx.x; t < n; t += 256)
            g_cand[b][base + t] = s[t];
        __syncthreads();
    }
}

/* ------- kernel 4b: global bitonic fallback (only if a segment overflowed) */
__global__ void __launch_bounds__(1024, 1)
sort_fallback_kernel() {
    int b = blockIdx.x;
    if (!g_segovf[b]) return;                 /* common case: exit */
    extern __shared__ unsigned long long s[];
    int tid = threadIdx.x;
    for (int i = tid; i < SORTN; i += blockDim.x) s[i] = g_cand[b][i];
    __syncthreads();
    for (int k = 2; k <= SORTN; k <<= 1) {
        for (int j = k >> 1; j > 0; j >>= 1) {
            for (int i = tid; i < SORTN; i += blockDim.x) {
                int ixj = i ^ j;
                if (ixj > i) {
                    unsigned long long x = s[i], y = s[ixj];
                    bool up = ((i & k) == 0);
                    if (up ? (x < y) : (x > y)) { s[i] = y; s[ixj] = x; }
                }
            }
            __syncthreads();
        }
    }
    for (int i = tid; i < SORTN; i += blockDim.x) g_cand[b][i] = s[i];
}

/* ------- kernel 4c: gather top-K rows + box decode ---------------------- */
__global__ void decode_kernel(const float* __restrict__ bbox,
                              const float* __restrict__ anchors) {
    int b = blockIdx.y;
    int i = blockIdx.x * blockDim.x + threadIdx.x;
    if (i >= KTOP) return;
    const float4* anc = (const float4*)(anchors + (size_t)b * NA * 4);
    const float4* dl  = (const float4*)(bbox    + (size_t)b * NA * 4);
    unsigned int idx = ~(unsigned int)(g_cand[b][i]);   /* low 32 inverted */
    float4 a4 = anc[idx];
    float4 r4 = dl[idx];
    float d0 = __fmul_rn(r4.x, 0.1f);
    float d1 = __fmul_rn(r4.y, 0.1f);
    float d2 = __fmul_rn(r4.z, 0.2f);
    float d3 = __fmul_rn(r4.w, 0.2f);
    float h  = __fsub_rn(a4.z, a4.x);
    float w  = __fsub_rn(a4.w, a4.y);
    float cy = __fadd_rn(__fadd_rn(a4.x, __fmul_rn(0.5f, h)), __fmul_rn(d0, h));
    float cx = __fadd_rn(__fadd_rn(a4.y, __fmul_rn(0.5f, w)), __fmul_rn(d1, w));
    float h2 = __fmul_rn(h, expf(d2));
    float w2 = __fmul_rn(w, expf(d3));
    float y1 = __fsub_rn(cy, __fmul_rn(0.5f, h2));
    float x1 = __fsub_rn(cx, __fmul_rn(0.5f, w2));
    float y2 = __fadd_rn(y1, h2);
    float x2 = __fadd_rn(x1, w2);
    y1 = fminf(fmaxf(y1, 0.0f), 1.0f);
    x1 = fminf(fmaxf(x1, 0.0f), 1.0f);
    y2 = fminf(fmaxf(y2, 0.0f), 1.0f);
    x2 = fminf(fmaxf(x2, 0.0f), 1.0f);
    g_boxes[b * KTOP + i] = make_float4(y1, x1, y2, x2);
    g_areas[b * KTOP + i] = __fmul_rn(__fsub_rn(y2, y1), __fsub_rn(x2, x1));
}

/* ------- kernel 5a: assign boxes to grid cells -------------------------- */
__global__ void cell_assign_kernel() {
    int b = blockIdx.y;
    int i = blockIdx.x * blockDim.x + threadIdx.x;
    if (i >= KTOP) return;
    float4 bx = g_boxes[b * KTOP + i];
    int cy0 = min(CELLG - 1, (int)(bx.x * CELLG));
    int cx0 = min(CELLG - 1, (int)(bx.y * CELLG));
    int cy1 = min(CELLG - 1, (int)(bx.z * CELLG));
    int cx1 = min(CELLG - 1, (int)(bx.w * CELLG));
    for (int cy = cy0; cy <= cy1; ++cy)
        for (int cx = cx0; cx <= cx1; ++cx) {
            int cell = cy * CELLG + cx;
            unsigned int pos = atomicAdd(&g_ccnt[b][cell], 1u);
            if (pos < CELLCAP) g_cells[b][cell][pos] = (unsigned int)i;
            else               g_cellovf[b] = 1u;
        }
}

/* ------- kernel 5b: per-cell pair evaluation (row-loop, exact dedup) ---- */
__global__ void __launch_bounds__(256)
cell_pairs_kernel() {
    int cell = blockIdx.x;
    int b    = blockIdx.y;
    int cellx = cell & (CELLG - 1);
    int celly = cell >> 4;
    __shared__ float4         sbx[CELLCAP];
    __shared__ unsigned short sid[CELLCAP];
    int n = (int)min(g_ccnt[b][cell], (unsigned int)CELLCAP);
    for (int t = threadIdx.x; t < n; t += blockDim.x) {
        unsigned int gi = g_cells[b][cell][t];
        sid[t] = (unsigned short)gi;
        sbx[t] = g_boxes[b * KTOP + gi];
    }
    __syncthreads();
    for (int a = threadIdx.x; a < n - 1; a += blockDim.x) {
        float4 A = sbx[a];
        float aA = __fmul_rn(__fsub_rn(A.z, A.x), __fsub_rn(A.w, A.y));
        int idA = (int)sid[a];
        for (int bq = a + 1; bq < n; ++bq) {
            float4 Bx = sbx[bq];
            float yy1 = fmaxf(A.x, Bx.x);
            float xx1 = fmaxf(A.y, Bx.y);
            float yy2 = fminf(A.z, Bx.z);
            float xx2 = fminf(A.w, Bx.w);
            float inter = __fmul_rn(fmaxf(__fsub_rn(yy2, yy1), 0.0f),
                                    fmaxf(__fsub_rn(xx2, xx1), 0.0f));
            if (inter > 0.0f) {
                int ccy = min(CELLG - 1, (int)(yy1 * CELLG));
                int ccx = min(CELLG - 1, (int)(xx1 * CELLG));
                if (ccy == celly && ccx == cellx) {
                    float aB = __fmul_rn(__fsub_rn(Bx.z, Bx.x),
                                         __fsub_rn(Bx.w, Bx.y));
                    float uni = __fsub_rn(__fadd_rn(aA, aB), inter);
                    if (uni > 0.0f && !(__fdiv_rn(inter, uni) <= 0.7f)) {
                        int ib = (int)sid[bq];
                        int i = min(idA, ib), j = max(idA, ib);
                        unsigned int pos = atomicAdd(&g_pcnt[b][i], 1u);
                        if (pos < SLOTS) {
                            g_padj[b][i][pos] = (unsigned int)j;
                        } else {
                            unsigned int sp2 = atomicAdd(&g_spillcnt[b], 1u);
                            if (sp2 < SPILLCAP)
                                g_spill[b][sp2] =
                                    ((unsigned int)i << 16) | (unsigned int)j;
                        }
                    }
                }
            }
        }
    }
}

/* ------- kernel 5c: brute-force fallback (only if a cell overflowed) ---- */
#define MBK_THREADS 256
#define MBK_RPW     8
#define MBK_ROWS    (8 * MBK_RPW)
#define MBK_CHUNK   2048

__global__ void __launch_bounds__(MBK_THREADS)
pair_fallback_kernel() {
    int b = blockIdx.y;
    if (!g_cellovf[b]) return;                  /* common case: exit */
    int rowbase = blockIdx.x * MBK_ROWS;
    int warp    = threadIdx.x >> 5;
    int lane    = threadIdx.x & 31;
    int i0      = rowbase + warp * MBK_RPW;

    __shared__ float4 sbox[MBK_CHUNK];
    const float4* boxes = g_boxes + b * KTOP;
    const float*  areas = g_areas + b * KTOP;

    float4 rb[MBK_RPW]; float ra[MBK_RPW];
#pragma unroll
    for (int r = 0; r < MBK_RPW; ++r) {
        int i = i0 + r;
        if (i < KTOP) { rb[r] = boxes[i]; ra[r] = areas[i]; }
        else { rb[r] = make_float4(0.f, 0.f, 0.f, 0.f); ra[r] = 0.f; }
    }
    for (int chunk = 0; chunk < KTOP; chunk += MBK_CHUNK) {
        int cn = min(MBK_CHUNK, KTOP - chunk);
        __syncthreads();
        for (int t = threadIdx.x; t < cn; t += MBK_THREADS)
            sbox[t] = boxes[chunk + t];
        __syncthreads();
        if (chunk + cn <= rowbase) continue;
        int wstart = (i0 + 1 > chunk) ? ((i0 + 1 - chunk) >> 5) : 0;
        int wend   = (cn + 31) >> 5;
        for (int wd = wstart; wd < wend; ++wd) {
            int j = chunk + wd * 32 + lane;
            float4 cbx = sbox[wd * 32 + lane];
            float cax = __fmul_rn(__fsub_rn(cbx.z, cbx.x),
                                  __fsub_rn(cbx.w, cbx.y));
            bool jok = (j < KTOP);
            unsigned int supmask = 0;
#pragma unroll
            for (int r = 0; r < MBK_RPW; ++r) {
                float yy1 = fmaxf(rb[r].x, cbx.x);
                float xx1 = fmaxf(rb[r].y, cbx.y);
                float yy2 = fminf(rb[r].z, cbx.z);
                float xx2 = fminf(rb[r].w, cbx.w);
                float inter = __fmul_rn(fmaxf(__fsub_rn(yy2, yy1), 0.0f),
                                        fmaxf(__fsub_rn(xx2, xx1), 0.0f));
                bool sup = false;
                if (inter > 0.0f && jok && j > i0 + r) {
                    float uni = __fsub_rn(__fadd_rn(ra[r], cax), inter);
                    if (uni > 0.0f)
                        sup = !(__fdiv_rn(inter, uni) <= 0.7f);
                }
                supmask |= sup ? (1u << r) : 0u;
            }
            if (__any_sync(0xFFFFFFFFu, supmask != 0u)) {
                while (supmask) {
                    int r = __ffs(supmask) - 1;
                    supmask &= supmask - 1u;
                    int i = i0 + r;
                    unsigned int pos = atomicAdd(&g_pcnt[b][i], 1u);
                    if (pos < SLOTS) {
                        g_padj[b][i][pos] = (unsigned int)j;
                    } else {
                        unsigned int sp2 = atomicAdd(&g_spillcnt[b], 1u);
                        if (sp2 < SPILLCAP)
                            g_spill[b][sp2] =
                                ((unsigned int)i << 16) | (unsigned int)j;
                    }
                }
            }
        }
    }
}

/* ------- kernel 6: sparse serial greedy pass ---------------------------- */
__global__ void __launch_bounds__(32, 1)
nms_serial_kernel(float* __restrict__ out) {
    int b    = blockIdx.x;
    int lane = threadIdx.x;
    __shared__ unsigned long long sbm[94];
    __shared__ unsigned long long szero[94];
    __shared__ unsigned char      scnt[KTOP];
    __shared__ int                s_picks[PROP];
    __shared__ int                s_ctl[2];

    const float* areas = g_areas + b * KTOP;

    for (int wu = lane; wu < 94; wu += 32)
        sbm[wu] = (wu < 93) ? ~0ull : ((1ull << 48) - 1ull);

    for (int wu = 0; wu < 94; ++wu) {
        int i1 = wu * 64 + lane;
        int i2 = i1 + 32;
        bool z1 = (i1 < KTOP) && (areas[i1] == 0.0f);
        bool z2 = (i2 < KTOP) && (areas[i2] == 0.0f);
        unsigned int lo = __ballot_sync(0xFFFFFFFFu, z1);
        unsigned int hi = __ballot_sync(0xFFFFFFFFu, z2);
        if (lane == 0)
            szero[wu] = ((unsigned long long)hi << 32) | lo;
    }

    for (int i = lane; i < KTOP; i += 32) {
        unsigned int c = g_pcnt[b][i];
        scnt[i] = (unsigned char)(c > 255u ? 255u : c);
    }
    __syncwarp();

    if (lane == 0) {
        int cur = 0, sp = 0, fill = -1;
        int sc = (int)g_spillcnt[b];
        if (sc > SPILLCAP) sc = SPILLCAP;
        while (sp < PROP) {
            int wu = cur >> 6;
            unsigned long long w =
                (wu < 94) ? (sbm[wu] & (~0ull << (cur & 63))) : 0ull;
            while (!w) {
                if (++wu >= 94) break;
                w = sbm[wu];
            }
            if (wu >= 94) break;
            int i = (wu << 6) + (__ffsll((long long)w) - 1);
            s_picks[sp++] = i;
            if ((szero[wu] >> (i & 63)) & 1ull) {
                fill = i;
                break;
            }
            cur = i + 1;
            int n = scnt[i];
            if (n) {
                const unsigned int* adj = g_padj[b][i];
                int mslots = n < SLOTS ? n : SLOTS;
                for (int t = 0; t < mslots; ++t) {
                    int j = (int)adj[t];
                    sbm[j >> 6] &= ~(1ull << (j & 63));
                }
                if (n > SLOTS) {
                    for (int k = 0; k < sc; ++k) {
                        unsigned int p = g_spill[b][k];
                        if ((int)(p >> 16) == i) {
                            int j = (int)(p & 0xFFFFu);
                            sbm[j >> 6] &= ~(1ull << (j & 63));
                        }
                    }
                }
            }
        }
        s_ctl[0] = sp;
        s_ctl[1] = fill;
    }
    __syncwarp();
    int step = s_ctl[0];
    int fill = s_ctl[1];

    for (int s2 = step + lane; s2 < PROP; s2 += 32) s_picks[s2] = fill;
    __syncwarp();
    const float4* boxes = g_boxes + b * KTOP;
    float4* o = (float4*)out + b * PROP;
    for (int s2 = lane; s2 < PROP; s2 += 32) {
        int p = s_picks[s2];
        o[s2] = (p >= 0) ? boxes[p] : make_float4(0.f, 0.f, 0.f, 0.f);
    }
}

/* ---------------- launch ------------------------------------------------ */
extern "C" void kernel_launch(void* const* d_in, const int* in_sizes, int n_in,
                              void* d_out, int out_size) {
    const float* probs   = (const float*)d_in[0];  /* (B, A, 2) */
    const float* bbox    = (const float*)d_in[1];  /* (B, A, 4) */
    const float* anchors = (const float*)d_in[2];  /* (B, A, 4) */
    float* out = (float*)d_out;                    /* (B, 1000, 4) */

    cudaFuncSetAttribute(sort_fallback_kernel,
                         cudaFuncAttributeMaxDynamicSharedMemorySize, SORTN * 8);

    clear_kernel<<<1024, 256>>>();
    dim3 hg(256, BATCH);
    hist_kernel<<<hg, 256>>>(probs);
    findthresh_kernel<<<BATCH, 256>>>();
    compact_kernel<<<hg, 256>>>(probs);
    dim3 sg(64, BATCH);
    segsort_kernel<<<sg, 256>>>();
    sort_fallback_kernel<<<BATCH, 1024, SORTN * 8>>>();
    dim3 dg((KTOP + 255) / 256, BATCH);
    decode_kernel<<<dg, 256>>>(bbox, anchors);
    dim3 ag((KTOP + 255) / 256, BATCH);
    cell_assign_kernel<<<ag, 256>>>();
    dim3 cg(NCELL, BATCH);
    cell_pairs_kernel<<<cg, 256>>>();
    dim3 fg((KTOP + MBK_ROWS - 1) / MBK_ROWS, BATCH);
    pair_fallback_kernel<<<fg, MBK_THREADS>>>();
    nms_serial_kernel<<<BATCH, 32>>>(out);
}

// round 15
// speedup vs baseline: 1.4211x; 1.1889x over previous
#include <cuda_runtime.h>
#include <math.h>

#define BATCH 8
#define NA    261888
#define KTOP  6000
#define PROP  1000
#define SHIFT 14
#define NBUCK (1 << 18)
#define CAP   8192
#define SORTN 8192
#define SEGP  1024

#define SLOTS    32
#define SPILLCAP 32768

#define CELLG    16
#define NCELL    (CELLG * CELLG)
#define CELLCAP  768

/* ---------------- device scratch (static: no allocation allowed) -------- */
__device__ unsigned int       g_hist[BATCH][NBUCK];
__device__ unsigned int       g_base[BATCH][NBUCK];
__device__ unsigned int       g_maxbucket[BATCH];
__device__ int                g_thresh[BATCH];
__device__ unsigned int       g_total[BATCH];
__device__ unsigned int       g_segovf[BATCH];
__device__ unsigned long long g_cand[BATCH][CAP];
__device__ float4             g_boxes[BATCH * KTOP];
__device__ float              g_areas[BATCH * KTOP];
__device__ unsigned int       g_pcnt[BATCH][KTOP];           /* pairs per row */
__device__ unsigned int       g_padj[BATCH][KTOP][SLOTS];    /* adjacency     */
__device__ unsigned int       g_spill[BATCH][SPILLCAP];      /* (i<<16)|j     */
__device__ unsigned int       g_spillcnt[BATCH];
__device__ unsigned int       g_ccnt[BATCH][NCELL];          /* boxes / cell  */
__device__ unsigned int       g_cells[BATCH][NCELL][CELLCAP];
__device__ unsigned int       g_cellovf[BATCH];              /* overflow flag */

/* order-preserving float -> uint key */
__device__ __forceinline__ unsigned int fkey(float s) {
    unsigned int u = __float_as_uint(s);
    return u ^ ((unsigned int)((int)u >> 31) | 0x80000000u);
}

/* ---------------- kernel 0: clear scratch ------------------------------ */
__global__ void clear_kernel() {
    size_t tid    = (size_t)blockIdx.x * blockDim.x + threadIdx.x;
    size_t stride = (size_t)gridDim.x * blockDim.x;
    uint4* h4 = (uint4*)&g_hist[0][0];
    size_t n4 = (size_t)BATCH * NBUCK / 4;
    uint4 z4 = make_uint4(0, 0, 0, 0);
    for (size_t i = tid; i < n4; i += stride) h4[i] = z4;
    unsigned long long* c = &g_cand[0][0];
    for (size_t i = tid; i < (size_t)BATCH * CAP; i += stride) c[i] = 0ull;
    unsigned int* pc = &g_pcnt[0][0];
    for (size_t i = tid; i < (size_t)BATCH * KTOP; i += stride) pc[i] = 0u;
    unsigned int* cc = &g_ccnt[0][0];
    for (size_t i = tid; i < (size_t)BATCH * NCELL; i += stride) cc[i] = 0u;
    if (tid < BATCH) {
        g_maxbucket[tid] = 0u; g_spillcnt[tid] = 0u;
        g_cellovf[tid] = 0u;  g_segovf[tid] = 0u;
    }
}

/* ---------------- kernel 1: per-batch bucket histogram ------------------ */
__global__ void hist_kernel(const float* __restrict__ probs) {
    int b = blockIdx.y;
    const float* p = probs + (size_t)b * NA * 2;
    unsigned int lmax = 0;
    for (int a = blockIdx.x * blockDim.x + threadIdx.x; a < NA;
         a += gridDim.x * blockDim.x) {
        unsigned int key = fkey(p[2 * a + 1]);
        unsigned int bk = key >> SHIFT;
        atomicAdd(&g_hist[b][bk], 1u);
        lmax = max(lmax, bk);
    }
    __shared__ unsigned int sm[256];
    sm[threadIdx.x] = lmax;
    __syncthreads();
    for (int o = 128; o > 0; o >>= 1) {
        if (threadIdx.x < o) sm[threadIdx.x] = max(sm[threadIdx.x], sm[threadIdx.x + o]);
        __syncthreads();
    }
    if (threadIdx.x == 0) atomicMax(&g_maxbucket[b], sm[0]);
}

/* ---------------- kernel 2: find threshold bucket, write fill bases ----- */
__global__ void findthresh_kernel() {
    int b = blockIdx.x, tid = threadIdx.x;
    __shared__ unsigned int scnt[256];
    __shared__ unsigned int s_running;
    if (tid == 0) s_running = 0;
    __syncthreads();
    int start = (int)g_maxbucket[b];
    for (int cs = start; cs >= 0; cs -= 256) {
        int bk = cs - tid;
        unsigned int c = (bk >= 0) ? g_hist[b][bk] : 0u;
        scnt[tid] = c;
        __syncthreads();
        for (int off = 1; off < 256; off <<= 1) {
            unsigned int v = (tid >= off) ? scnt[tid - off] : 0u;
            __syncthreads();
            scnt[tid] += v;
            __syncthreads();
        }
        unsigned int incl = scnt[tid];
        unsigned int excl = incl - c;
        unsigned int run = s_running;
        if (bk >= 0 && run + excl < KTOP) {
            g_hist[b][bk] = run + excl;       /* counting-sort fill base */
            g_base[b][bk] = run + excl;       /* snapshot for segsort    */
            if (run + incl >= KTOP) {
                g_thresh[b] = bk;
                g_total[b]  = run + incl;
            }
        }
        __syncthreads();
        if (tid == 0) s_running = run + scnt[255];
        __syncthreads();
        if (s_running >= KTOP) break;
    }
}

/* ---------------- kernel 3: compact candidates (grouped by bucket) ------ */
__global__ void compact_kernel(const float* __restrict__ probs) {
    int b = blockIdx.y;
    int tb = g_thresh[b];
    const float* p = probs + (size_t)b * NA * 2;
    for (int a = blockIdx.x * blockDim.x + threadIdx.x; a < NA;
         a += gridDim.x * blockDim.x) {
        unsigned int key = fkey(p[2 * a + 1]);
        unsigned int bk = key >> SHIFT;
        if ((int)bk >= tb) {
            unsigned int pos = atomicAdd(&g_hist[b][bk], 1u);
            if (pos < CAP)
                g_cand[b][pos] =
                    ((unsigned long long)key << 32) | (unsigned int)(~a);
        }
    }
}

/* ------- kernel 4a: per-bucket block bitonic sort ----------------------- */
__global__ void __launch_bounds__(256)
segsort_kernel() {
    int b  = blockIdx.y;
    int tb = g_thresh[b];
    int mb = (int)g_maxbucket[b];
    __shared__ unsigned long long s[SEGP];
    for (int bk = tb + blockIdx.x; bk <= mb; bk += gridDim.x) {
        unsigned int base = g_base[b][bk];
        unsigned int end  = g_hist[b][bk];    /* end offset after compact */
        if (end > CAP) { g_segovf[b] = 1u; continue; }
        int n = (int)(end - base);
        if (n <= 1) continue;
        if (n > SEGP) { g_segovf[b] = 1u; continue; }
        for (int t = threadIdx.x; t < SEGP; t += 256)
            s[t] = (t < n) ? g_cand[b][base + t] : 0ull;   /* 0 sorts last */
        __syncthreads();
        for (int k = 2; k <= SEGP; k <<= 1) {
            for (int j = k >> 1; j > 0; j >>= 1) {
                for (int t = threadIdx.x; t < SEGP; t += 256) {
                    int ixj = t ^ j;
                    if (ixj > t) {
                        unsigned long long x = s[t], y = s[ixj];
                        bool up = ((t & k) == 0);          /* descending */
                        if (up ? (x < y) : (x > y)) { s[t] = y; s[ixj] = x; }
                    }
                }
                __syncthreads();
            }
        }
        for (int t = threadIdx.x; t < n; t += 256)
            g_cand[b][base + t] = s[t];
        __syncthreads();
    }
}

/* ------- kernel 4b: global bitonic fallback (only if a segment overflowed) */
__global__ void __launch_bounds__(1024, 1)
sort_fallback_kernel() {
    int b = blockIdx.x;
    if (!g_segovf[b]) return;                 /* common case: exit */
    extern __shared__ unsigned long long s[];
    int tid = threadIdx.x;
    for (int i = tid; i < SORTN; i += blockDim.x) s[i] = g_cand[b][i];
    __syncthreads();
    for (int k = 2; k <= SORTN; k <<= 1) {
        for (int j = k >> 1; j > 0; j >>= 1) {
            for (int i = tid; i < SORTN; i += blockDim.x) {
                int ixj = i ^ j;
                if (ixj > i) {
                    unsigned long long x = s[i], y = s[ixj];
                    bool up = ((i & k) == 0);
                    if (up ? (x < y) : (x > y)) { s[i] = y; s[ixj] = x; }
                }
            }
            __syncthreads();
        }
    }
    for (int i = tid; i < SORTN; i += blockDim.x) g_cand[b][i] = s[i];
}

/* ------- kernel 4c: gather + box decode + cell assign (fused) ----------- */
__global__ void decode_assign_kernel(const float* __restrict__ bbox,
                                     const float* __restrict__ anchors) {
    int b = blockIdx.y;
    int i = blockIdx.x * blockDim.x + threadIdx.x;
    if (i >= KTOP) return;
    const float4* anc = (const float4*)(anchors + (size_t)b * NA * 4);
    const float4* dl  = (const float4*)(bbox    + (size_t)b * NA * 4);
    unsigned int idx = ~(unsigned int)(g_cand[b][i]);   /* low 32 inverted */
    float4 a4 = anc[idx];
    float4 r4 = dl[idx];
    float d0 = __fmul_rn(r4.x, 0.1f);
    float d1 = __fmul_rn(r4.y, 0.1f);
    float d2 = __fmul_rn(r4.z, 0.2f);
    float d3 = __fmul_rn(r4.w, 0.2f);
    float h  = __fsub_rn(a4.z, a4.x);
    float w  = __fsub_rn(a4.w, a4.y);
    float cy = __fadd_rn(__fadd_rn(a4.x, __fmul_rn(0.5f, h)), __fmul_rn(d0, h));
    float cx = __fadd_rn(__fadd_rn(a4.y, __fmul_rn(0.5f, w)), __fmul_rn(d1, w));
    float h2 = __fmul_rn(h, expf(d2));
    float w2 = __fmul_rn(w, expf(d3));
    float y1 = __fsub_rn(cy, __fmul_rn(0.5f, h2));
    float x1 = __fsub_rn(cx, __fmul_rn(0.5f, w2));
    float y2 = __fadd_rn(y1, h2);
    float x2 = __fadd_rn(x1, w2);
    y1 = fminf(fmaxf(y1, 0.0f), 1.0f);
    x1 = fminf(fmaxf(x1, 0.0f), 1.0f);
    y2 = fminf(fmaxf(y2, 0.0f), 1.0f);
    x2 = fminf(fmaxf(x2, 0.0f), 1.0f);
    g_boxes[b * KTOP + i] = make_float4(y1, x1, y2, x2);
    g_areas[b * KTOP + i] = __fmul_rn(__fsub_rn(y2, y1), __fsub_rn(x2, x1));
    /* cell assignment (identical math to the former cell_assign_kernel) */
    int cy0 = min(CELLG - 1, (int)(y1 * CELLG));
    int cx0 = min(CELLG - 1, (int)(x1 * CELLG));
    int cy1 = min(CELLG - 1, (int)(y2 * CELLG));
    int cx1 = min(CELLG - 1, (int)(x2 * CELLG));
    for (int cyy = cy0; cyy <= cy1; ++cyy)
        for (int cxx = cx0; cxx <= cx1; ++cxx) {
            int cell = cyy * CELLG + cxx;
            unsigned int pos = atomicAdd(&g_ccnt[b][cell], 1u);
            if (pos < CELLCAP) g_cells[b][cell][pos] = (unsigned int)i;
            else               g_cellovf[b] = 1u;
        }
}

/* ------- kernel 5b: per-cell pair evaluation (row-loop, exact dedup) ---- */
__global__ void __launch_bounds__(256)
cell_pairs_kernel() {
    int cell = blockIdx.x;
    int b    = blockIdx.y;
    int cellx = cell & (CELLG - 1);
    int celly = cell >> 4;
    __shared__ float4         sbx[CELLCAP];
    __shared__ unsigned short sid[CELLCAP];
    int n = (int)min(g_ccnt[b][cell], (unsigned int)CELLCAP);
    for (int t = threadIdx.x; t < n; t += blockDim.x) {
        unsigned int gi = g_cells[b][cell][t];
        sid[t] = (unsigned short)gi;
        sbx[t] = g_boxes[b * KTOP + gi];
    }
    __syncthreads();
    for (int a = threadIdx.x; a < n - 1; a += blockDim.x) {
        float4 A = sbx[a];
        float aA = __fmul_rn(__fsub_rn(A.z, A.x), __fsub_rn(A.w, A.y));
        int idA = (int)sid[a];
        for (int bq = a + 1; bq < n; ++bq) {
            float4 Bx = sbx[bq];
            float yy1 = fmaxf(A.x, Bx.x);
            float xx1 = fmaxf(A.y, Bx.y);
            float yy2 = fminf(A.z, Bx.z);
            float xx2 = fminf(A.w, Bx.w);
            float inter = __fmul_rn(fmaxf(__fsub_rn(yy2, yy1), 0.0f),
                                    fmaxf(__fsub_rn(xx2, xx1), 0.0f));
            if (inter > 0.0f) {
                int ccy = min(CELLG - 1, (int)(yy1 * CELLG));
                int ccx = min(CELLG - 1, (int)(xx1 * CELLG));
                if (ccy == celly && ccx == cellx) {
                    float aB = __fmul_rn(__fsub_rn(Bx.z, Bx.x),
                                         __fsub_rn(Bx.w, Bx.y));
                    float uni = __fsub_rn(__fadd_rn(aA, aB), inter);
                    if (uni > 0.0f && !(__fdiv_rn(inter, uni) <= 0.7f)) {
                        int ib = (int)sid[bq];
                        int i = min(idA, ib), j = max(idA, ib);
                        unsigned int pos = atomicAdd(&g_pcnt[b][i], 1u);
                        if (pos < SLOTS) {
                            g_padj[b][i][pos] = (unsigned int)j;
                        } else {
                            unsigned int sp2 = atomicAdd(&g_spillcnt[b], 1u);
                            if (sp2 < SPILLCAP)
                                g_spill[b][sp2] =
                                    ((unsigned int)i << 16) | (unsigned int)j;
                        }
                    }
                }
            }
        }
    }
}

/* ------- kernel 5c: brute-force fallback (only if a cell overflowed) ---- */
#define MBK_THREADS 256
#define MBK_RPW     8
#define MBK_ROWS    (8 * MBK_RPW)
#define MBK_CHUNK   2048

__global__ void __launch_bounds__(MBK_THREADS)
pair_fallback_kernel() {
    int b = blockIdx.y;
    if (!g_cellovf[b]) return;                  /* common case: exit */
    int rowbase = blockIdx.x * MBK_ROWS;
    int warp    = threadIdx.x >> 5;
    int lane    = threadIdx.x & 31;
    int i0      = rowbase + warp * MBK_RPW;

    __shared__ float4 sbox[MBK_CHUNK];
    const float4* boxes = g_boxes + b * KTOP;
    const float*  areas = g_areas + b * KTOP;

    float4 rb[MBK_RPW]; float ra[MBK_RPW];
#pragma unroll
    for (int r = 0; r < MBK_RPW; ++r) {
        int i = i0 + r;
        if (i < KTOP) { rb[r] = boxes[i]; ra[r] = areas[i]; }
        else { rb[r] = make_float4(0.f, 0.f, 0.f, 0.f); ra[r] = 0.f; }
    }
    for (int chunk = 0; chunk < KTOP; chunk += MBK_CHUNK) {
        int cn = min(MBK_CHUNK, KTOP - chunk);
        __syncthreads();
        for (int t = threadIdx.x; t < cn; t += MBK_THREADS)
            sbox[t] = boxes[chunk + t];
        __syncthreads();
        if (chunk + cn <= rowbase) continue;
        int wstart = (i0 + 1 > chunk) ? ((i0 + 1 - chunk) >> 5) : 0;
        int wend   = (cn + 31) >> 5;
        for (int wd = wstart; wd < wend; ++wd) {
            int j = chunk + wd * 32 + lane;
            float4 cbx = sbox[wd * 32 + lane];
            float cax = __fmul_rn(__fsub_rn(cbx.z, cbx.x),
                                  __fsub_rn(cbx.w, cbx.y));
            bool jok = (j < KTOP);
            unsigned int supmask = 0;
#pragma unroll
            for (int r = 0; r < MBK_RPW; ++r) {
                float yy1 = fmaxf(rb[r].x, cbx.x);
                float xx1 = fmaxf(rb[r].y, cbx.y);
                float yy2 = fminf(rb[r].z, cbx.z);
                float xx2 = fminf(rb[r].w, cbx.w);
                float inter = __fmul_rn(fmaxf(__fsub_rn(yy2, yy1), 0.0f),
                                        fmaxf(__fsub_rn(xx2, xx1), 0.0f));
                bool sup = false;
                if (inter > 0.0f && jok && j > i0 + r) {
                    float uni = __fsub_rn(__fadd_rn(ra[r], cax), inter);
                    if (uni > 0.0f)
                        sup = !(__fdiv_rn(inter, uni) <= 0.7f);
                }
                supmask |= sup ? (1u << r) : 0u;
            }
            if (__any_sync(0xFFFFFFFFu, supmask != 0u)) {
                while (supmask) {
                    int r = __ffs(supmask) - 1;
                    supmask &= supmask - 1u;
                    int i = i0 + r;
                    unsigned int pos = atomicAdd(&g_pcnt[b][i], 1u);
                    if (pos < SLOTS) {
                        g_padj[b][i][pos] = (unsigned int)j;
                    } else {
                        unsigned int sp2 = atomicAdd(&g_spillcnt[b], 1u);
                        if (sp2 < SPILLCAP)
                            g_spill[b][sp2] =
                                ((unsigned int)i << 16) | (unsigned int)j;
                    }
                }
            }
        }
    }
}

/* ------- kernel 6: sparse serial greedy pass (word-wise scan) ----------- */
__global__ void __launch_bounds__(32, 1)
nms_serial_kernel(float* __restrict__ out) {
    int b    = blockIdx.x;
    int lane = threadIdx.x;
    __shared__ unsigned long long sbm[94];     /* valid bitmap             */
    __shared__ unsigned long long szero[94];   /* zero-area flags          */
    __shared__ unsigned long long spair[94];   /* has-pairs flags          */
    __shared__ unsigned char      scnt[KTOP];  /* per-row pair count (cap) */
    __shared__ int                s_picks[PROP];
    __shared__ int                s_ctl[2];    /* step, fill */

    const float* areas = g_areas + b * KTOP;

    for (int wu = lane; wu < 94; wu += 32)
        sbm[wu] = (wu < 93) ? ~0ull : ((1ull << 48) - 1ull);

    /* pair counts -> smem bytes (clamped) */
    for (int i = lane; i < KTOP; i += 32) {
        unsigned int c = g_pcnt[b][i];
        scnt[i] = (unsigned char)(c > 255u ? 255u : c);
    }
    __syncwarp();

    /* zero-area + has-pairs flag bitmaps via ballots */
    for (int wu = 0; wu < 94; ++wu) {
        int i1 = wu * 64 + lane;
        int i2 = i1 + 32;
        bool z1 = (i1 < KTOP) && (areas[i1] == 0.0f);
        bool z2 = (i2 < KTOP) && (areas[i2] == 0.0f);
        bool p1 = (i1 < KTOP) && (scnt[i1] != 0);
        bool p2 = (i2 < KTOP) && (scnt[i2] != 0);
        unsigned int zlo = __ballot_sync(0xFFFFFFFFu, z1);
        unsigned int zhi = __ballot_sync(0xFFFFFFFFu, z2);
        unsigned int plo = __ballot_sync(0xFFFFFFFFu, p1);
        unsigned int phi = __ballot_sync(0xFFFFFFFFu, p2);
        if (lane == 0) {
            szero[wu] = ((unsigned long long)zhi << 32) | zlo;
            spair[wu] = ((unsigned long long)phi << 32) | plo;
        }
    }
    __syncwarp();

    if (lane == 0) {
        int sp = 0, fill = -1;
        int sc = (int)g_spillcnt[b];
        if (sc > SPILLCAP) sc = SPILLCAP;
        for (int wu = 0; wu < 94 && sp < PROP && fill < 0; ++wu) {
            unsigned long long w = sbm[wu];          /* snapshot: 1 LDS/word */
            if (!w) continue;
            unsigned long long zw = szero[wu];
            unsigned long long pw = spair[wu];
            while (w && sp < PROP) {
                int bx = __ffsll((long long)w) - 1;
                int i = (wu << 6) + bx;
                s_picks[sp++] = i;
                if ((zw >> bx) & 1ull) {             /* degenerate: repeats */
                    fill = i;
                    break;
                }
                w &= w - 1ull;
                if ((pw >> bx) & 1ull) {             /* rare: has suppressions */
                    int n = scnt[i];
                    const unsigned int* adj = g_padj[b][i];
                    int mslots = n < SLOTS ? n : SLOTS;
                    for (int t = 0; t < mslots; ++t) {
                        int j = (int)adj[t];         /* j > i always */
                        if ((j >> 6) == wu) w &= ~(1ull << (j & 63));
                        else sbm[j >> 6] &= ~(1ull << (j & 63));
                    }
                    if (n > SLOTS) {                 /* overflow path */
                        for (int k = 0; k < sc; ++k) {
                            unsigned int p = g_spill[b][k];
                            if ((int)(p >> 16) == i) {
                                int j = (int)(p & 0xFFFFu);
                                if ((j >> 6) == wu) w &= ~(1ull << (j & 63));
                                else sbm[j >> 6] &= ~(1ull << (j & 63));
                            }
                        }
                    }
                }
            }
        }
        s_ctl[0] = sp;
        s_ctl[1] = fill;
    }
    __syncwarp();
    int step = s_ctl[0];
    int fill = s_ctl[1];

    for (int s2 = step + lane; s2 < PROP; s2 += 32) s_picks[s2] = fill;
    __syncwarp();
    const float4* boxes = g_boxes + b * KTOP;
    float4* o = (float4*)out + b * PROP;
    for (int s2 = lane; s2 < PROP; s2 += 32) {
        int p = s_picks[s2];
        o[s2] = (p >= 0) ? boxes[p] : make_float4(0.f, 0.f, 0.f, 0.f);
    }
}

/* ---------------- launch ------------------------------------------------ */
extern "C" void kernel_launch(void* const* d_in, const int* in_sizes, int n_in,
                              void* d_out, int out_size) {
    const float* probs   = (const float*)d_in[0];  /* (B, A, 2) */
    const float* bbox    = (const float*)d_in[1];  /* (B, A, 4) */
    const float* anchors = (const float*)d_in[2];  /* (B, A, 4) */
    float* out = (float*)d_out;                    /* (B, 1000, 4) */

    cudaFuncSetAttribute(sort_fallback_kernel,
                         cudaFuncAttributeMaxDynamicSharedMemorySize, SORTN * 8);

    clear_kernel<<<1024, 256>>>();
    dim3 hg(256, BATCH);
    hist_kernel<<<hg, 256>>>(probs);
    findthresh_kernel<<<BATCH, 256>>>();
    compact_kernel<<<hg, 256>>>(probs);
    dim3 sg(64, BATCH);
    segsort_kernel<<<sg, 256>>>();
    sort_fallback_kernel<<<BATCH, 1024, SORTN * 8>>>();
    dim3 dg((KTOP + 255) / 256, BATCH);
    decode_assign_kernel<<<dg, 256>>>(bbox, anchors);
    dim3 cg(NCELL, BATCH);
    cell_pairs_kernel<<<cg, 256>>>();
    dim3 fg((KTOP + MBK_ROWS - 1) / MBK_ROWS, BATCH);
    pair_fallback_kernel<<<fg, MBK_THREADS>>>();
    nms_serial_kernel<<<BATCH, 32>>>(out);
}

// round 16
// speedup vs baseline: 1.5158x; 1.0667x over previous
#include <cuda_runtime.h>
#include <math.h>

#define BATCH 8
#define NA    261888
#define KTOP  6000
#define PROP  1000
#define SHIFT 14
#define NBUCK (1 << 18)
#define CAP   8192
#define SORTN 8192
#define SEGP  1024

#define SLOTS    32
#define SPILLCAP 32768

#define CELLG    16
#define NCELL    (CELLG * CELLG)
#define CELLCAP  768

/* ---------------- device scratch (static: no allocation allowed) -------- */
__device__ unsigned int       g_hist[BATCH][NBUCK];
__device__ unsigned int       g_base[BATCH][NBUCK];
__device__ unsigned int       g_maxbucket[BATCH];
__device__ int                g_thresh[BATCH];
__device__ unsigned int       g_total[BATCH];
__device__ unsigned int       g_segovf[BATCH];
__device__ unsigned long long g_cand[BATCH][CAP];
__device__ float4             g_boxes[BATCH * KTOP];
__device__ float              g_areas[BATCH * KTOP];
__device__ unsigned int       g_pcnt[BATCH][KTOP];           /* pairs per row */
__device__ unsigned int       g_padj[BATCH][KTOP][SLOTS];    /* adjacency     */
__device__ unsigned int       g_spill[BATCH][SPILLCAP];      /* (i<<16)|j     */
__device__ unsigned int       g_spillcnt[BATCH];
__device__ unsigned int       g_ccnt[BATCH][NCELL];          /* boxes / cell  */
__device__ unsigned int       g_cells[BATCH][NCELL][CELLCAP];
__device__ unsigned int       g_cellovf[BATCH];              /* overflow flag */
__device__ unsigned long long g_zerobm[BATCH][94];           /* zero-area     */
__device__ unsigned long long g_pairbm[BATCH][94];           /* has-pairs     */

/* order-preserving float -> uint key */
__device__ __forceinline__ unsigned int fkey(float s) {
    unsigned int u = __float_as_uint(s);
    return u ^ ((unsigned int)((int)u >> 31) | 0x80000000u);
}

/* ---------------- kernel 0: clear scratch ------------------------------ */
__global__ void clear_kernel() {
    size_t tid    = (size_t)blockIdx.x * blockDim.x + threadIdx.x;
    size_t stride = (size_t)gridDim.x * blockDim.x;
    uint4* h4 = (uint4*)&g_hist[0][0];
    size_t n4 = (size_t)BATCH * NBUCK / 4;
    uint4 z4 = make_uint4(0, 0, 0, 0);
    for (size_t i = tid; i < n4; i += stride) h4[i] = z4;
    unsigned long long* c = &g_cand[0][0];
    for (size_t i = tid; i < (size_t)BATCH * CAP; i += stride) c[i] = 0ull;
    unsigned int* pc = &g_pcnt[0][0];
    for (size_t i = tid; i < (size_t)BATCH * KTOP; i += stride) pc[i] = 0u;
    unsigned int* cc = &g_ccnt[0][0];
    for (size_t i = tid; i < (size_t)BATCH * NCELL; i += stride) cc[i] = 0u;
    unsigned long long* zb = &g_zerobm[0][0];
    for (size_t i = tid; i < (size_t)BATCH * 94 * 2; i += stride) zb[i] = 0ull;
    if (tid < BATCH) {
        g_maxbucket[tid] = 0u; g_spillcnt[tid] = 0u;
        g_cellovf[tid] = 0u;  g_segovf[tid] = 0u;
    }
}

/* ---------------- kernel 1: per-batch bucket histogram (float4) --------- */
__global__ void hist_kernel(const float* __restrict__ probs) {
    int b = blockIdx.y;
    const float4* p4 = (const float4*)(probs + (size_t)b * NA * 2);
    unsigned int lmax = 0;
    for (int v = blockIdx.x * blockDim.x + threadIdx.x; v < NA / 2;
         v += gridDim.x * blockDim.x) {
        float4 q = p4[v];                 /* two (p0,p1) pairs */
        unsigned int bk1 = fkey(q.y) >> SHIFT;
        unsigned int bk2 = fkey(q.w) >> SHIFT;
        atomicAdd(&g_hist[b][bk1], 1u);
        atomicAdd(&g_hist[b][bk2], 1u);
        lmax = max(lmax, max(bk1, bk2));
    }
    __shared__ unsigned int sm[256];
    sm[threadIdx.x] = lmax;
    __syncthreads();
    for (int o = 128; o > 0; o >>= 1) {
        if (threadIdx.x < o) sm[threadIdx.x] = max(sm[threadIdx.x], sm[threadIdx.x + o]);
        __syncthreads();
    }
    if (threadIdx.x == 0) atomicMax(&g_maxbucket[b], sm[0]);
}

/* ---------------- kernel 2: find threshold bucket, write fill bases ----- */
__global__ void findthresh_kernel() {
    int b = blockIdx.x, tid = threadIdx.x;
    __shared__ unsigned int scnt[256];
    __shared__ unsigned int s_running;
    if (tid == 0) s_running = 0;
    __syncthreads();
    int start = (int)g_maxbucket[b];
    for (int cs = start; cs >= 0; cs -= 256) {
        int bk = cs - tid;
        unsigned int c = (bk >= 0) ? g_hist[b][bk] : 0u;
        scnt[tid] = c;
        __syncthreads();
        for (int off = 1; off < 256; off <<= 1) {
            unsigned int v = (tid >= off) ? scnt[tid - off] : 0u;
            __syncthreads();
            scnt[tid] += v;
            __syncthreads();
        }
        unsigned int incl = scnt[tid];
        unsigned int excl = incl - c;
        unsigned int run = s_running;
        if (bk >= 0 && run + excl < KTOP) {
            g_hist[b][bk] = run + excl;       /* counting-sort fill base */
            g_base[b][bk] = run + excl;       /* snapshot for segsort    */
            if (run + incl >= KTOP) {
                g_thresh[b] = bk;
                g_total[b]  = run + incl;
            }
        }
        __syncthreads();
        if (tid == 0) s_running = run + scnt[255];
        __syncthreads();
        if (s_running >= KTOP) break;
    }
}

/* ---------------- kernel 3: compact candidates (float4) ----------------- */
__global__ void compact_kernel(const float* __restrict__ probs) {
    int b = blockIdx.y;
    int tb = g_thresh[b];
    const float4* p4 = (const float4*)(probs + (size_t)b * NA * 2);
    for (int v = blockIdx.x * blockDim.x + threadIdx.x; v < NA / 2;
         v += gridDim.x * blockDim.x) {
        float4 q = p4[v];
        unsigned int key1 = fkey(q.y);
        unsigned int key2 = fkey(q.w);
        unsigned int bk1 = key1 >> SHIFT;
        unsigned int bk2 = key2 >> SHIFT;
        if ((int)bk1 >= tb) {
            unsigned int pos = atomicAdd(&g_hist[b][bk1], 1u);
            if (pos < CAP)
                g_cand[b][pos] =
                    ((unsigned long long)key1 << 32) | (unsigned int)(~(2 * v));
        }
        if ((int)bk2 >= tb) {
            unsigned int pos = atomicAdd(&g_hist[b][bk2], 1u);
            if (pos < CAP)
                g_cand[b][pos] =
                    ((unsigned long long)key2 << 32) | (unsigned int)(~(2 * v + 1));
        }
    }
}

/* ------- kernel 4a: per-bucket block bitonic sort ----------------------- */
__global__ void __launch_bounds__(256)
segsort_kernel() {
    int b  = blockIdx.y;
    int tb = g_thresh[b];
    int mb = (int)g_maxbucket[b];
    __shared__ unsigned long long s[SEGP];
    for (int bk = tb + blockIdx.x; bk <= mb; bk += gridDim.x) {
        unsigned int base = g_base[b][bk];
        unsigned int end  = g_hist[b][bk];    /* end offset after compact */
        if (end > CAP) { g_segovf[b] = 1u; continue; }
        int n = (int)(end - base);
        if (n <= 1) continue;
        if (n > SEGP) { g_segovf[b] = 1u; continue; }
        for (int t = threadIdx.x; t < SEGP; t += 256)
            s[t] = (t < n) ? g_cand[b][base + t] : 0ull;   /* 0 sorts last */
        __syncthreads();
        for (int k = 2; k <= SEGP; k <<= 1) {
            for (int j = k >> 1; j > 0; j >>= 1) {
                for (int t = threadIdx.x; t < SEGP; t += 256) {
                    int ixj = t ^ j;
                    if (ixj > t) {
                        unsigned long long x = s[t], y = s[ixj];
                        bool up = ((t & k) == 0);          /* descending */
                        if (up ? (x < y) : (x > y)) { s[t] = y; s[ixj] = x; }
                    }
                }
                __syncthreads();
            }
        }
        for (int t = threadIdx.x; t < n; t += 256)
            g_cand[b][base + t] = s[t];
        __syncthreads();
    }
}

/* ------- kernel 4b: global bitonic fallback (only if a segment overflowed) */
__global__ void __launch_bounds__(1024, 1)
sort_fallback_kernel() {
    int b = blockIdx.x;
    if (!g_segovf[b]) return;                 /* common case: exit */
    extern __shared__ unsigned long long s[];
    int tid = threadIdx.x;
    for (int i = tid; i < SORTN; i += blockDim.x) s[i] = g_cand[b][i];
    __syncthreads();
    for (int k = 2; k <= SORTN; k <<= 1) {
        for (int j = k >> 1; j > 0; j >>= 1) {
            for (int i = tid; i < SORTN; i += blockDim.x) {
                int ixj = i ^ j;
                if (ixj > i) {
                    unsigned long long x = s[i], y = s[ixj];
                    bool up = ((i & k) == 0);
                    if (up ? (x < y) : (x > y)) { s[i] = y; s[ixj] = x; }
                }
            }
            __syncthreads();
        }
    }
    for (int i = tid; i < SORTN; i += blockDim.x) g_cand[b][i] = s[i];
}

/* ------- kernel 4c: gather + box decode + cell assign (fused) ----------- */
__global__ void decode_assign_kernel(const float* __restrict__ bbox,
                                     const float* __restrict__ anchors) {
    int b = blockIdx.y;
    int i = blockIdx.x * blockDim.x + threadIdx.x;
    if (i >= KTOP) return;
    const float4* anc = (const float4*)(anchors + (size_t)b * NA * 4);
    const float4* dl  = (const float4*)(bbox    + (size_t)b * NA * 4);
    unsigned int idx = ~(unsigned int)(g_cand[b][i]);   /* low 32 inverted */
    float4 a4 = anc[idx];
    float4 r4 = dl[idx];
    float d0 = __fmul_rn(r4.x, 0.1f);
    float d1 = __fmul_rn(r4.y, 0.1f);
    float d2 = __fmul_rn(r4.z, 0.2f);
    float d3 = __fmul_rn(r4.w, 0.2f);
    float h  = __fsub_rn(a4.z, a4.x);
    float w  = __fsub_rn(a4.w, a4.y);
    float cy = __fadd_rn(__fadd_rn(a4.x, __fmul_rn(0.5f, h)), __fmul_rn(d0, h));
    float cx = __fadd_rn(__fadd_rn(a4.y, __fmul_rn(0.5f, w)), __fmul_rn(d1, w));
    float h2 = __fmul_rn(h, expf(d2));
    float w2 = __fmul_rn(w, expf(d3));
    float y1 = __fsub_rn(cy, __fmul_rn(0.5f, h2));
    float x1 = __fsub_rn(cx, __fmul_rn(0.5f, w2));
    float y2 = __fadd_rn(y1, h2);
    float x2 = __fadd_rn(x1, w2);
    y1 = fminf(fmaxf(y1, 0.0f), 1.0f);
    x1 = fminf(fmaxf(x1, 0.0f), 1.0f);
    y2 = fminf(fmaxf(y2, 0.0f), 1.0f);
    x2 = fminf(fmaxf(x2, 0.0f), 1.0f);
    float area = __fmul_rn(__fsub_rn(y2, y1), __fsub_rn(x2, x1));
    g_boxes[b * KTOP + i] = make_float4(y1, x1, y2, x2);
    g_areas[b * KTOP + i] = area;
    if (area == 0.0f)
        atomicOr(&g_zerobm[b][i >> 6], 1ull << (i & 63));
    /* cell assignment (identical math to the former cell_assign_kernel) */
    int cy0 = min(CELLG - 1, (int)(y1 * CELLG));
    int cx0 = min(CELLG - 1, (int)(x1 * CELLG));
    int cy1 = min(CELLG - 1, (int)(y2 * CELLG));
    int cx1 = min(CELLG - 1, (int)(x2 * CELLG));
    for (int cyy = cy0; cyy <= cy1; ++cyy)
        for (int cxx = cx0; cxx <= cx1; ++cxx) {
            int cell = cyy * CELLG + cxx;
            unsigned int pos = atomicAdd(&g_ccnt[b][cell], 1u);
            if (pos < CELLCAP) g_cells[b][cell][pos] = (unsigned int)i;
            else               g_cellovf[b] = 1u;
        }
}

/* ------- kernel 5b: per-cell pair evaluation (row-loop, exact dedup) ---- */
__global__ void __launch_bounds__(256)
cell_pairs_kernel() {
    int cell = blockIdx.x;
    int b    = blockIdx.y;
    int cellx = cell & (CELLG - 1);
    int celly = cell >> 4;
    __shared__ float4         sbx[CELLCAP];
    __shared__ unsigned short sid[CELLCAP];
    int n = (int)min(g_ccnt[b][cell], (unsigned int)CELLCAP);
    for (int t = threadIdx.x; t < n; t += blockDim.x) {
        unsigned int gi = g_cells[b][cell][t];
        sid[t] = (unsigned short)gi;
        sbx[t] = g_boxes[b * KTOP + gi];
    }
    __syncthreads();
    for (int a = threadIdx.x; a < n - 1; a += blockDim.x) {
        float4 A = sbx[a];
        float aA = __fmul_rn(__fsub_rn(A.z, A.x), __fsub_rn(A.w, A.y));
        int idA = (int)sid[a];
        for (int bq = a + 1; bq < n; ++bq) {
            float4 Bx = sbx[bq];
            float yy1 = fmaxf(A.x, Bx.x);
            float xx1 = fmaxf(A.y, Bx.y);
            float yy2 = fminf(A.z, Bx.z);
            float xx2 = fminf(A.w, Bx.w);
            float inter = __fmul_rn(fmaxf(__fsub_rn(yy2, yy1), 0.0f),
                                    fmaxf(__fsub_rn(xx2, xx1), 0.0f));
            if (inter > 0.0f) {
                int ccy = min(CELLG - 1, (int)(yy1 * CELLG));
                int ccx = min(CELLG - 1, (int)(xx1 * CELLG));
                if (ccy == celly && ccx == cellx) {
                    float aB = __fmul_rn(__fsub_rn(Bx.z, Bx.x),
                                         __fsub_rn(Bx.w, Bx.y));
                    float uni = __fsub_rn(__fadd_rn(aA, aB), inter);
                    if (uni > 0.0f && !(__fdiv_rn(inter, uni) <= 0.7f)) {
                        int ib = (int)sid[bq];
                        int i = min(idA, ib), j = max(idA, ib);
                        unsigned int pos = atomicAdd(&g_pcnt[b][i], 1u);
                        if (pos == 0u)
                            atomicOr(&g_pairbm[b][i >> 6], 1ull << (i & 63));
                        if (pos < SLOTS) {
                            g_padj[b][i][pos] = (unsigned int)j;
                        } else {
                            unsigned int sp2 = atomicAdd(&g_spillcnt[b], 1u);
                            if (sp2 < SPILLCAP)
                                g_spill[b][sp2] =
                                    ((unsigned int)i << 16) | (unsigned int)j;
                        }
                    }
                }
            }
        }
    }
}

/* ------- kernel 5c: brute-force fallback (only if a cell overflowed) ---- */
#define MBK_THREADS 256
#define MBK_RPW     8
#define MBK_ROWS    (8 * MBK_RPW)
#define MBK_CHUNK   2048

__global__ void __launch_bounds__(MBK_THREADS)
pair_fallback_kernel() {
    int b = blockIdx.y;
    if (!g_cellovf[b]) return;                  /* common case: exit */
    int rowbase = blockIdx.x * MBK_ROWS;
    int warp    = threadIdx.x >> 5;
    int lane    = threadIdx.x & 31;
    int i0      = rowbase + warp * MBK_RPW;

    __shared__ float4 sbox[MBK_CHUNK];
    const float4* boxes = g_boxes + b * KTOP;
    const float*  areas = g_areas + b * KTOP;

    float4 rb[MBK_RPW]; float ra[MBK_RPW];
#pragma unroll
    for (int r = 0; r < MBK_RPW; ++r) {
        int i = i0 + r;
        if (i < KTOP) { rb[r] = boxes[i]; ra[r] = areas[i]; }
        else { rb[r] = make_float4(0.f, 0.f, 0.f, 0.f); ra[r] = 0.f; }
    }
    for (int chunk = 0; chunk < KTOP; chunk += MBK_CHUNK) {
        int cn = min(MBK_CHUNK, KTOP - chunk);
        __syncthreads();
        for (int t = threadIdx.x; t < cn; t += MBK_THREADS)
            sbox[t] = boxes[chunk + t];
        __syncthreads();
        if (chunk + cn <= rowbase) continue;
        int wstart = (i0 + 1 > chunk) ? ((i0 + 1 - chunk) >> 5) : 0;
        int wend   = (cn + 31) >> 5;
        for (int wd = wstart; wd < wend; ++wd) {
            int j = chunk + wd * 32 + lane;
            float4 cbx = sbox[wd * 32 + lane];
            float cax = __fmul_rn(__fsub_rn(cbx.z, cbx.x),
                                  __fsub_rn(cbx.w, cbx.y));
            bool jok = (j < KTOP);
            unsigned int supmask = 0;
#pragma unroll
            for (int r = 0; r < MBK_RPW; ++r) {
                float yy1 = fmaxf(rb[r].x, cbx.x);
                float xx1 = fmaxf(rb[r].y, cbx.y);
                float yy2 = fminf(rb[r].z, cbx.z);
                float xx2 = fminf(rb[r].w, cbx.w);
                float inter = __fmul_rn(fmaxf(__fsub_rn(yy2, yy1), 0.0f),
                                        fmaxf(__fsub_rn(xx2, xx1), 0.0f));
                bool sup = false;
                if (inter > 0.0f && jok && j > i0 + r) {
                    float uni = __fsub_rn(__fadd_rn(ra[r], cax), inter);
                    if (uni > 0.0f)
                        sup = !(__fdiv_rn(inter, uni) <= 0.7f);
                }
                supmask |= sup ? (1u << r) : 0u;
            }
            if (__any_sync(0xFFFFFFFFu, supmask != 0u)) {
                while (supmask) {
                    int r = __ffs(supmask) - 1;
                    supmask &= supmask - 1u;
                    int i = i0 + r;
                    unsigned int pos = atomicAdd(&g_pcnt[b][i], 1u);
                    if (pos == 0u)
                        atomicOr(&g_pairbm[b][i >> 6], 1ull << (i & 63));
                    if (pos < SLOTS) {
                        g_padj[b][i][pos] = (unsigned int)j;
                    } else {
                        unsigned int sp2 = atomicAdd(&g_spillcnt[b], 1u);
                        if (sp2 < SPILLCAP)
                            g_spill[b][sp2] =
                                ((unsigned int)i << 16) | (unsigned int)j;
                    }
                }
            }
        }
    }
}

/* ------- kernel 6: sparse serial greedy pass (word-wise scan) ----------- */
__global__ void __launch_bounds__(32, 1)
nms_serial_kernel(float* __restrict__ out) {
    int b    = blockIdx.x;
    int lane = threadIdx.x;
    __shared__ unsigned long long sbm[94];     /* valid bitmap             */
    __shared__ unsigned long long szero[94];   /* zero-area flags          */
    __shared__ unsigned long long spair[94];   /* has-pairs flags          */
    __shared__ unsigned char      scnt[KTOP];  /* per-row pair count (cap) */
    __shared__ int                s_picks[PROP];
    __shared__ int                s_ctl[2];    /* step, fill */

    /* parallel init: bitmaps precomputed by upstream kernels */
    for (int wu = lane; wu < 94; wu += 32) {
        sbm[wu]   = (wu < 93) ? ~0ull : ((1ull << 48) - 1ull);
        szero[wu] = g_zerobm[b][wu];
        spair[wu] = g_pairbm[b][wu];
    }
    for (int i = lane; i < KTOP; i += 32) {
        unsigned int c = g_pcnt[b][i];
        scnt[i] = (unsigned char)(c > 255u ? 255u : c);
    }
    __syncwarp();

    if (lane == 0) {
        int sp = 0, fill = -1;
        int sc = (int)g_spillcnt[b];
        if (sc > SPILLCAP) sc = SPILLCAP;
        for (int wu = 0; wu < 94 && sp < PROP && fill < 0; ++wu) {
            unsigned long long w = sbm[wu];          /* snapshot: 1 LDS/word */
            if (!w) continue;
            unsigned long long zw = szero[wu];
            unsigned long long pw = spair[wu];
            while (w && sp < PROP) {
                int bx = __ffsll((long long)w) - 1;
                int i = (wu << 6) + bx;
                s_picks[sp++] = i;
                if ((zw >> bx) & 1ull) {             /* degenerate: repeats */
                    fill = i;
                    break;
                }
                w &= w - 1ull;
                if ((pw >> bx) & 1ull) {             /* rare: has suppressions */
                    int n = scnt[i];
                    const unsigned int* adj = g_padj[b][i];
                    int mslots = n < SLOTS ? n : SLOTS;
                    for (int t = 0; t < mslots; ++t) {
                        int j = (int)adj[t];         /* j > i always */
                        if ((j >> 6) == wu) w &= ~(1ull << (j & 63));
                        else sbm[j >> 6] &= ~(1ull << (j & 63));
                    }
                    if (n > SLOTS) {                 /* overflow path */
                        for (int k = 0; k < sc; ++k) {
                            unsigned int p = g_spill[b][k];
                            if ((int)(p >> 16) == i) {
                                int j = (int)(p & 0xFFFFu);
                                if ((j >> 6) == wu) w &= ~(1ull << (j & 63));
                                else sbm[j >> 6] &= ~(1ull << (j & 63));
                            }
                        }
                    }
                }
            }
        }
        s_ctl[0] = sp;
        s_ctl[1] = fill;
    }
    __syncwarp();
    int step = s_ctl[0];
    int fill = s_ctl[1];

    for (int s2 = step + lane; s2 < PROP; s2 += 32) s_picks[s2] = fill;
    __syncwarp();
    const float4* boxes = g_boxes + b * KTOP;
    float4* o = (float4*)out + b * PROP;
    for (int s2 = lane; s2 < PROP; s2 += 32) {
        int p = s_picks[s2];
        o[s2] = (p >= 0) ? boxes[p] : make_float4(0.f, 0.f, 0.f, 0.f);
    }
}

/* ---------------- launch ------------------------------------------------ */
extern "C" void kernel_launch(void* const* d_in, const int* in_sizes, int n_in,
                              void* d_out, int out_size) {
    const float* probs   = (const float*)d_in[0];  /* (B, A, 2) */
    const float* bbox    = (const float*)d_in[1];  /* (B, A, 4) */
    const float* anchors = (const float*)d_in[2];  /* (B, A, 4) */
    float* out = (float*)d_out;                    /* (B, 1000, 4) */

    cudaFuncSetAttribute(sort_fallback_kernel,
                         cudaFuncAttributeMaxDynamicSharedMemorySize, SORTN * 8);

    clear_kernel<<<1024, 256>>>();
    dim3 hg(256, BATCH);
    hist_kernel<<<hg, 256>>>(probs);
    findthresh_kernel<<<BATCH, 256>>>();
    compact_kernel<<<hg, 256>>>(probs);
    dim3 sg(64, BATCH);
    segsort_kernel<<<sg, 256>>>();
    sort_fallback_kernel<<<BATCH, 1024, SORTN * 8>>>();
    dim3 dg((KTOP + 255) / 256, BATCH);
    decode_assign_kernel<<<dg, 256>>>(bbox, anchors);
    dim3 cg(NCELL, BATCH);
    cell_pairs_kernel<<<cg, 256>>>();
    dim3 fg((KTOP + MBK_ROWS - 1) / MBK_ROWS, BATCH);
    pair_fallback_kernel<<<fg, MBK_THREADS>>>();
    nms_serial_kernel<<<BATCH, 32>>>(out);
}